// round 4
// baseline (speedup 1.0000x reference)
#include <cuda_runtime.h>
#include <cuda_bf16.h>
#include <cstdio>

// Problem constants (match reference)
#define NN 20000
#define NE 320000
#define H_DIM 128
#define KIN 162      // NUM_SEM + MAXPP + FS
#define ETN 4
#define LDE 260      // 2*H + ETN
#define NEG_INF (-3.402823466e38f)

// ---------------- scratch (static device allocation is allowed) ----------------
__device__ float g_cf0[NN * H_DIM];
__device__ float g_P1[NN * H_DIM];
__device__ float g_P2[NN * H_DIM];
__device__ float g_cf1[NN * H_DIM];
// column-max slots: [0:128) ipf0, [128:256) ipf1, [256:384) iter2-msg max,
// [384:512) geo max, [512:640) skip max
__device__ unsigned g_cm[640];

// monotone float<->uint encoding for atomicMax on signed floats
__device__ __forceinline__ unsigned encf(float f) {
    unsigned u = __float_as_uint(f);
    return (u & 0x80000000u) ? ~u : (u | 0x80000000u);
}
__device__ __forceinline__ float decf(unsigned e) {
    unsigned u = (e & 0x80000000u) ? (e ^ 0x80000000u) : ~e;
    return __uint_as_float(u);
}
__device__ __forceinline__ float leaky(float x) { return x > 0.f ? x : 0.01f * x; }

// ---------------- init ----------------
__global__ void init_zero(float* cf1, unsigned* cm) {
    int i = blockIdx.x * blockDim.x + threadIdx.x;
    int stride = gridDim.x * blockDim.x;
    float4 z = make_float4(0.f, 0.f, 0.f, 0.f);
    for (int t = i; t < (NN * H_DIM) / 4; t += stride)
        reinterpret_cast<float4*>(cf1)[t] = z;
    if (i < 640) cm[i] = 0u;
}

// ---------------- node GEMM: out[N,128] = X[N,K] @ W.T (+bias) (*exists) ----------------
// block: 128 rows x 128 cols, 256 threads, per-thread 16x4 register tile
template <bool STORE, bool COLMAX, bool HAS_BIAS, bool HAS_EXISTS>
__global__ void node_gemm(const float* __restrict__ X, int N, int K, int ldx,
                          const float* __restrict__ W, int ldw,
                          const float* __restrict__ bias,
                          const float* __restrict__ exists,
                          float* __restrict__ out,
                          unsigned* __restrict__ cm)
{
    __shared__ float Xs[128][17];
    __shared__ float Ws[16][129];
    const int tid = threadIdx.x;
    const int tcol = tid & 31;
    const int trow = tid >> 5;
    const int rowBase = blockIdx.x * 128;

    float acc[16][4];
#pragma unroll
    for (int i = 0; i < 16; i++)
#pragma unroll
        for (int q = 0; q < 4; q++) acc[i][q] = 0.f;

    for (int k0 = 0; k0 < K; k0 += 16) {
#pragma unroll
        for (int t = 0; t < 8; t++) {   // X tile: 128x16
            int idx = tid + t * 256;
            int r = idx >> 4, kk = idx & 15;
            int gr = rowBase + r, gk = k0 + kk;
            float v = 0.f;
            if (gr < N && gk < K) v = X[gr * ldx + gk];
            Xs[r][kk] = v;
        }
#pragma unroll
        for (int t = 0; t < 8; t++) {   // W tile: 128x16 (transposed into Ws[k][j])
            int idx = tid + t * 256;
            int j = idx >> 4, kk = idx & 15;
            int gk = k0 + kk;
            Ws[kk][j] = (gk < K) ? W[j * ldw + gk] : 0.f;
        }
        __syncthreads();
#pragma unroll
        for (int kk = 0; kk < 16; kk++) {
            float wv[4];
#pragma unroll
            for (int q = 0; q < 4; q++) wv[q] = Ws[kk][tcol + 32 * q];
#pragma unroll
            for (int i = 0; i < 16; i++) {
                float xv = Xs[trow * 16 + i][kk];
#pragma unroll
                for (int q = 0; q < 4; q++) acc[i][q] = fmaf(xv, wv[q], acc[i][q]);
            }
        }
        __syncthreads();
    }

    float bv[4];
#pragma unroll
    for (int q = 0; q < 4; q++) bv[q] = HAS_BIAS ? bias[tcol + 32 * q] : 0.f;

    unsigned tm[4] = {0u, 0u, 0u, 0u};
#pragma unroll
    for (int i = 0; i < 16; i++) {
        int gr = rowBase + trow * 16 + i;
        if (gr < N) {
            float ex = HAS_EXISTS ? exists[gr] : 1.f;
#pragma unroll
            for (int q = 0; q < 4; q++) {
                float v = (acc[i][q] + bv[q]) * ex;
                if (STORE) out[gr * H_DIM + tcol + 32 * q] = v;
                if (COLMAX) {
                    unsigned e = encf(v);
                    if (e > tm[q]) tm[q] = e;
                }
            }
        }
    }
    if (COLMAX) {
        __shared__ unsigned smax[128];
        for (int t = tid; t < 128; t += 256) smax[t] = 0u;
        __syncthreads();
#pragma unroll
        for (int q = 0; q < 4; q++) atomicMax(&smax[tcol + 32 * q], tm[q]);
        __syncthreads();
        for (int t = tid; t < 128; t += 256)
            if (smax[t]) atomicMax(&cm[t], smax[t]);
    }
}

// ---------------- iter-1 edge pass: scatter-max messages into cf1 ----------------
// msg[e] = leaky(P1[from] + P2[to] + ef[e]@We.T + b); cf1[from] = max(cf1[from], msg, 0)
__global__ void edge_scatter(const float* __restrict__ P1, const float* __restrict__ P2,
                             const int* __restrict__ eidx, const float* __restrict__ ef,
                             const float* __restrict__ Wit,  // edge_w[0] base, ld=260
                             const float* __restrict__ bit,  // edge_b[0]
                             float* __restrict__ cf1, int nE)
{
    __shared__ float wesT[4][128];
    __shared__ float bsh[128];
    const int tid = threadIdx.x;
    if (tid < 128) {
#pragma unroll
        for (int k = 0; k < 4; k++) wesT[k][tid] = Wit[tid * LDE + 256 + k];
        bsh[tid] = bit[tid];
    }
    __syncthreads();
    const int warp = tid >> 5, lane = tid & 31;
    const int h0 = lane * 4;
    float wk[4][4], bb[4];
#pragma unroll
    for (int j = 0; j < 4; j++) {
        bb[j] = bsh[h0 + j];
#pragma unroll
        for (int k = 0; k < 4; k++) wk[k][j] = wesT[k][h0 + j];
    }

    for (int e = blockIdx.x * 8 + warp; e < nE; e += gridDim.x * 8) {
        int from = eidx[2 * e];
        int to = eidx[2 * e + 1];
        float4 e4 = *reinterpret_cast<const float4*>(ef + 4 * e);
        float4 p1 = *reinterpret_cast<const float4*>(P1 + from * H_DIM + h0);
        float4 p2 = *reinterpret_cast<const float4*>(P2 + to * H_DIM + h0);
        float pa[4] = {p1.x + p2.x, p1.y + p2.y, p1.z + p2.z, p1.w + p2.w};
        int* dst = reinterpret_cast<int*>(cf1 + from * H_DIM + h0);
#pragma unroll
        for (int j = 0; j < 4; j++) {
            float m = pa[j] + e4.x * wk[0][j] + e4.y * wk[1][j] +
                      e4.z * wk[2][j] + e4.w * wk[3][j] + bb[j];
            // leaky(m) <= 0 never beats the 0-initialized target, so only
            // positive m (where leaky is identity) can update.
            if (m > 0.f) atomicMax(dst + j, __float_as_int(m));
        }
    }
}

// ---------------- iter-2 edge pass: column-max of messages only ----------------
__global__ void edge_colmax(const float* __restrict__ P1, const float* __restrict__ P2,
                            const int* __restrict__ eidx, const float* __restrict__ ef,
                            const float* __restrict__ Wit,  // edge_w[1] base
                            const float* __restrict__ bit,  // edge_b[1]
                            unsigned* __restrict__ cm, int nE)
{
    __shared__ float wesT[4][128];
    __shared__ float bsh[128];
    __shared__ unsigned smax[128];
    const int tid = threadIdx.x;
    if (tid < 128) {
#pragma unroll
        for (int k = 0; k < 4; k++) wesT[k][tid] = Wit[tid * LDE + 256 + k];
        bsh[tid] = bit[tid];
    }
    for (int t = tid; t < 128; t += 256) smax[t] = 0u;
    __syncthreads();
    const int warp = tid >> 5, lane = tid & 31;
    const int h0 = lane * 4;
    float wk[4][4], bb[4];
#pragma unroll
    for (int j = 0; j < 4; j++) {
        bb[j] = bsh[h0 + j];
#pragma unroll
        for (int k = 0; k < 4; k++) wk[k][j] = wesT[k][h0 + j];
    }
    float rm[4] = {NEG_INF, NEG_INF, NEG_INF, NEG_INF};

    for (int e = blockIdx.x * 8 + warp; e < nE; e += gridDim.x * 8) {
        int from = eidx[2 * e];
        int to = eidx[2 * e + 1];
        float4 e4 = *reinterpret_cast<const float4*>(ef + 4 * e);
        float4 p1 = *reinterpret_cast<const float4*>(P1 + from * H_DIM + h0);
        float4 p2 = *reinterpret_cast<const float4*>(P2 + to * H_DIM + h0);
        float pa[4] = {p1.x + p2.x, p1.y + p2.y, p1.z + p2.z, p1.w + p2.w};
#pragma unroll
        for (int j = 0; j < 4; j++) {
            float m = pa[j] + e4.x * wk[0][j] + e4.y * wk[1][j] +
                      e4.z * wk[2][j] + e4.w * wk[3][j] + bb[j];
            float lm = leaky(m);
            rm[j] = fmaxf(rm[j], lm);
        }
    }
#pragma unroll
    for (int j = 0; j < 4; j++)
        if (rm[j] > NEG_INF) atomicMax(&smax[h0 + j], encf(rm[j]));
    __syncthreads();
    if (tid < 128 && smax[tid]) atomicMax(&cm[tid], smax[tid]);
}

// ---------------- column max of cf1 (values >= 0) ----------------
__global__ void colmax128(const float* __restrict__ x, int N, unsigned* __restrict__ cm)
{
    int h = threadIdx.x;  // 128 threads
    float m = NEG_INF;
    for (int row = blockIdx.x; row < N; row += gridDim.x)
        m = fmaxf(m, x[row * H_DIM + h]);
    if (m > NEG_INF) atomicMax(&cm[h], encf(m));
}

// ---------------- parent_feat ----------------
__global__ void final_feat(const unsigned* __restrict__ cm,
                           const float* __restrict__ sec_w,
                           const float* __restrict__ sec_b,
                           float* __restrict__ out)
{
    __shared__ float ipf[384];
    int h = threadIdx.x;  // 128
    ipf[h]       = decf(cm[h]);                    // ipf0 (stage A colmax)
    ipf[128 + h] = decf(cm[128 + h]);              // ipf1 (cf1 colmax, >=0)
    ipf[256 + h] = fmaxf(0.f, decf(cm[256 + h]));  // ipf2 = max(0, msg colmax)
    __syncthreads();
    float s = sec_b[h];
    const float* wr = sec_w + h * 384;
#pragma unroll 8
    for (int j = 0; j < 384; j++) s = fmaf(ipf[j], wr[j], s);
    out[h] = leaky(s);
}

// ---------------- parent_geo_feat ----------------
__global__ void final_geo(const unsigned* __restrict__ cm,  // +384: geo, +512: skip
                          const float* __restrict__ sgw, const float* __restrict__ sgb,
                          const float* __restrict__ gnw, const float* __restrict__ gnb,
                          float* __restrict__ out)
{
    __shared__ float pg[128];
    __shared__ float tbuf[128];
    int h = threadIdx.x;  // 128
    pg[h] = leaky(decf(cm[384 + h]));
    float sg = leaky(decf(cm[512 + h]));
    __syncthreads();
    float t = sgb[h];
    const float* wr = sgw + h * 128;
#pragma unroll 8
    for (int j = 0; j < 128; j++) t = fmaf(pg[j], wr[j], t);
    tbuf[h] = t;
    __syncthreads();
    int g0 = (h >> 3) << 3;  // group of 8 channels
    float mu = 0.f;
#pragma unroll
    for (int j = 0; j < 8; j++) mu += tbuf[g0 + j];
    mu *= 0.125f;
    float var = 0.f;
#pragma unroll
    for (int j = 0; j < 8; j++) {
        float d = tbuf[g0 + j] - mu;
        var = fmaf(d, d, var);
    }
    var *= 0.125f;
    float xn = (t - mu) * rsqrtf(var + 1e-5f);
    float y = xn * gnw[h] + gnb[h];
    out[128 + h] = leaky(sg + y);
}

// ---------------- launch ----------------
extern "C" void kernel_launch(void* const* d_in, const int* in_sizes, int n_in,
                              void* d_out, int out_size)
{
    const float* child_feats = (const float*)d_in[0];   // (1,N,162)
    const float* child_geo   = (const float*)d_in[1];   // (1,N,128)
    const float* exists      = (const float*)d_in[2];   // (1,N,1)
    const float* ef          = (const float*)d_in[3];   // (1,E,4)
    const int*   eidx        = (const int*)d_in[4];     // (1,E,2)
    const float* op_w  = (const float*)d_in[5];         // (128,162)
    const float* op_b  = (const float*)d_in[6];
    const float* sec_w = (const float*)d_in[7];         // (128,384)
    const float* sec_b = (const float*)d_in[8];
    const float* ew    = (const float*)d_in[9];         // (2,128,260)
    const float* eb    = (const float*)d_in[10];        // (2,128)
    const float* gw    = (const float*)d_in[11];        // (128,128)
    const float* gb    = (const float*)d_in[12];
    const float* sgw   = (const float*)d_in[13];        // (128,128)
    const float* sgb   = (const float*)d_in[14];
    const float* gnw   = (const float*)d_in[15];
    const float* gnb   = (const float*)d_in[16];
    const float* skw   = (const float*)d_in[17];        // (128,128)
    const float* skb   = (const float*)d_in[18];
    float* out = (float*)d_out;

    const int N  = in_sizes[2];       // 20000
    const int nE = in_sizes[4] / 2;   // 320000

    float *cf0, *P1, *P2, *cf1;
    unsigned* cm;
    cudaGetSymbolAddress((void**)&cf0, g_cf0);
    cudaGetSymbolAddress((void**)&P1, g_P1);
    cudaGetSymbolAddress((void**)&P2, g_P2);
    cudaGetSymbolAddress((void**)&cf1, g_cf1);
    cudaGetSymbolAddress((void**)&cm, g_cm);

    const int gemmBlocks = (N + 127) / 128;

    // 0) zero cf1 + colmax slots
    init_zero<<<1280, 256>>>(cf1, cm);

    // 1) stage A: cf0 = (child_feats @ op_w.T + op_b) * exists ; colmax -> cm[0:128)
    node_gemm<true, true, true, true><<<gemmBlocks, 256>>>(
        child_feats, N, KIN, KIN, op_w, KIN, op_b, exists, cf0, cm);

    // 2) P1 = cf0 @ edge_w[0][:,0:128].T ; P2 = cf0 @ edge_w[0][:,128:256].T
    node_gemm<true, false, false, false><<<gemmBlocks, 256>>>(
        cf0, N, H_DIM, H_DIM, ew, LDE, nullptr, nullptr, P1, nullptr);
    node_gemm<true, false, false, false><<<gemmBlocks, 256>>>(
        cf0, N, H_DIM, H_DIM, ew + 128, LDE, nullptr, nullptr, P2, nullptr);

    // 3) iter-1 edge pass: scatter-max into cf1
    edge_scatter<<<3040, 256>>>(P1, P2, eidx, ef, ew, eb, cf1, nE);

    // 4) ipf1 = colmax(cf1) -> cm[128:256)
    colmax128<<<512, 128>>>(cf1, N, cm + 128);

    // 5) Q1/Q2 from cf1 with edge_w[1] (reuse P buffers)
    node_gemm<true, false, false, false><<<gemmBlocks, 256>>>(
        cf1, N, H_DIM, H_DIM, ew + LDE * 128, LDE, nullptr, nullptr, P1, nullptr);
    node_gemm<true, false, false, false><<<gemmBlocks, 256>>>(
        cf1, N, H_DIM, H_DIM, ew + LDE * 128 + 128, LDE, nullptr, nullptr, P2, nullptr);

    // 6) iter-2 edge pass: msg colmax only -> cm[256:384)
    edge_colmax<<<1184, 256>>>(P1, P2, eidx, ef, ew + LDE * 128, eb + 128, cm + 256, nE);

    // 7) geo + skip column maxes (no store) -> cm[384:512), cm[512:640)
    node_gemm<false, true, true, true><<<gemmBlocks, 256>>>(
        child_geo, N, H_DIM, H_DIM, gw, H_DIM, gb, exists, nullptr, cm + 384);
    node_gemm<false, true, true, true><<<gemmBlocks, 256>>>(
        child_geo, N, H_DIM, H_DIM, skw, H_DIM, skb, exists, nullptr, cm + 512);

    // 8) heads
    final_feat<<<1, 128>>>(cm, sec_w, sec_b, out);
    final_geo<<<1, 128>>>(cm, sgw, sgb, gnw, gnb, out);
}

// round 6
// speedup vs baseline: 1.0271x; 1.0271x over previous
#include <cuda_runtime.h>
#include <cuda_bf16.h>
#include <cstdio>

// Problem constants (match reference)
#define NN 20000
#define NE 320000
#define H_DIM 128
#define KIN 162      // NUM_SEM + MAXPP + FS
#define ETN 4
#define LDE 260      // 2*H + ETN
#define NEG_INF (-3.402823466e38f)

typedef unsigned long long u64;

// packed fp32x2 FMA (sm_100+): d = a*b + d elementwise on the two f32 halves
__device__ __forceinline__ void ffma2(u64& d, u64 a, u64 b) {
    asm("fma.rn.f32x2 %0, %1, %2, %0;" : "+l"(d) : "l"(a), "l"(b));
}

// ---------------- scratch (static device allocation is allowed) ----------------
__device__ float g_cf0[NN * H_DIM];
__device__ float g_P1[NN * H_DIM];
__device__ float g_P2[NN * H_DIM];
__device__ float g_cf1[NN * H_DIM];
// column-max slots: [0:128) ipf0, [128:256) ipf1, [256:384) iter2-msg max,
// [384:512) geo max, [512:640) skip max
__device__ unsigned g_cm[640];

// monotone float<->uint encoding for atomicMax on signed floats
__device__ __forceinline__ unsigned encf(float f) {
    unsigned u = __float_as_uint(f);
    return (u & 0x80000000u) ? ~u : (u | 0x80000000u);
}
__device__ __forceinline__ float decf(unsigned e) {
    unsigned u = (e & 0x80000000u) ? (e ^ 0x80000000u) : ~e;
    return __uint_as_float(u);
}
__device__ __forceinline__ float leaky(float x) { return x > 0.f ? x : 0.01f * x; }

// ---------------- init ----------------
__global__ void init_zero(float* cf1, unsigned* cm) {
    int i = blockIdx.x * blockDim.x + threadIdx.x;
    int stride = gridDim.x * blockDim.x;
    float4 z = make_float4(0.f, 0.f, 0.f, 0.f);
    for (int t = i; t < (NN * H_DIM) / 4; t += stride)
        reinterpret_cast<float4*>(cf1)[t] = z;
    if (i < 640) cm[i] = 0u;
}

// ---------------- node GEMM v2: out[N,128] = X[N,K] @ W.T (+bias) (*exists) --------
// block: 128 rows x 128 cols, 256 threads; per-thread 8x8 tile held as
// 8 rows x 4 col-pair f32x2 accumulators, driven by FFMA2.
// X is staged duplicated+transposed in smem: Xd[kk][(2r)^swz] = Xd[..+1] = x[r]
// with swz = ((kk>>1)&7)<<2  (bank-spreading XOR that preserves 16B vector loads).
template <bool STORE, bool COLMAX, bool HAS_BIAS, bool HAS_EXISTS, bool ALIGNED>
__global__ void __launch_bounds__(256, 2)
node_gemm2(const float* __restrict__ X, int N, int K, int ldx,
           const float* __restrict__ W, int ldw,
           const float* __restrict__ bias,
           const float* __restrict__ exists,
           float* __restrict__ out,
           unsigned* __restrict__ cm)
{
    __shared__ __align__(16) float Xd[16 * 256];   // [kk][dup-pos]
    __shared__ __align__(16) float Ws2[16 * 132];  // [kk][col], padded row

    const int tid = threadIdx.x;
    const int tr = tid >> 4;    // 0..15 -> rows tr*8 .. tr*8+7
    const int tc = tid & 15;    // 0..15 -> cols tc*8 .. tc*8+7
    const int rowBase = blockIdx.x * 128;

    u64 acc[8][4];
#pragma unroll
    for (int i = 0; i < 8; i++)
#pragma unroll
        for (int c = 0; c < 4; c++) acc[i][c] = 0ull;

    for (int k0 = 0; k0 < K; k0 += 16) {
        // ---- stage X (transpose + duplicate) ----
        if (ALIGNED) {
#pragma unroll
            for (int t = 0; t < 2; t++) {
                int idx = tid + t * 256;
                int r = idx >> 2, kq = idx & 3;
                int gr = rowBase + r;
                float4 f = make_float4(0.f, 0.f, 0.f, 0.f);
                if (gr < N)
                    f = *reinterpret_cast<const float4*>(X + gr * ldx + k0 + kq * 4);
                float vj[4] = {f.x, f.y, f.z, f.w};
#pragma unroll
                for (int j = 0; j < 4; j++) {
                    int kk = kq * 4 + j;
                    int swz = ((kk >> 1) & 7) << 2;
                    int pos = (2 * r) ^ swz;
                    *reinterpret_cast<float2*>(&Xd[kk * 256 + pos]) =
                        make_float2(vj[j], vj[j]);
                }
            }
        } else {
#pragma unroll
            for (int t = 0; t < 8; t++) {
                int idx = tid + t * 256;
                int r = idx >> 4, kk = idx & 15;
                int gr = rowBase + r, gk = k0 + kk;
                float v = 0.f;
                if (gr < N && gk < K) v = X[gr * ldx + gk];
                int swz = ((kk >> 1) & 7) << 2;
                int pos = (2 * r) ^ swz;
                *reinterpret_cast<float2*>(&Xd[kk * 256 + pos]) = make_float2(v, v);
            }
        }
        // ---- stage W ----
#pragma unroll
        for (int t = 0; t < 8; t++) {
            int idx = tid + t * 256;
            int c = idx >> 4, kk = idx & 15;
            int gk = k0 + kk;
            Ws2[kk * 132 + c] = (gk < K) ? W[c * ldw + gk] : 0.f;
        }
        __syncthreads();

        // ---- compute ----
#pragma unroll
        for (int kk = 0; kk < 16; kk++) {
            const int swz = ((kk >> 1) & 7) << 2;
            const float* xbase = &Xd[kk * 256];
            u64 xr[8];
#pragma unroll
            for (int m = 0; m < 4; m++) {
                ulonglong2 u = *reinterpret_cast<const ulonglong2*>(
                    xbase + (((16 * tr + 4 * m) ^ swz)));
                xr[2 * m]     = u.x;   // dup(row 8tr+2m)
                xr[2 * m + 1] = u.y;   // dup(row 8tr+2m+1)
            }
            const float* wbase = &Ws2[kk * 132 + tc * 8];
            ulonglong2 w0 = *reinterpret_cast<const ulonglong2*>(wbase);
            ulonglong2 w1 = *reinterpret_cast<const ulonglong2*>(wbase + 4);
            u64 wv[4] = {w0.x, w0.y, w1.x, w1.y};   // col pairs (0,1)(2,3)(4,5)(6,7)
#pragma unroll
            for (int i = 0; i < 8; i++)
#pragma unroll
                for (int cp = 0; cp < 4; cp++)
                    ffma2(acc[i][cp], xr[i], wv[cp]);
        }
        __syncthreads();
    }

    // ---- epilogue ----
    float bv[8];
#pragma unroll
    for (int j = 0; j < 8; j++) bv[j] = HAS_BIAS ? bias[tc * 8 + j] : 0.f;

    unsigned tm[8];
#pragma unroll
    for (int j = 0; j < 8; j++) tm[j] = 0u;

#pragma unroll
    for (int i = 0; i < 8; i++) {
        int gr = rowBase + tr * 8 + i;
        if (gr < N) {
            float ex = HAS_EXISTS ? exists[gr] : 1.f;
            float v[8];
#pragma unroll
            for (int cp = 0; cp < 4; cp++) {
                float2 f = *reinterpret_cast<float2*>(&acc[i][cp]);
                v[2 * cp]     = (f.x + bv[2 * cp]) * ex;
                v[2 * cp + 1] = (f.y + bv[2 * cp + 1]) * ex;
            }
            if (STORE) {
                *reinterpret_cast<float4*>(out + gr * H_DIM + tc * 8) =
                    make_float4(v[0], v[1], v[2], v[3]);
                *reinterpret_cast<float4*>(out + gr * H_DIM + tc * 8 + 4) =
                    make_float4(v[4], v[5], v[6], v[7]);
            }
            if (COLMAX) {
#pragma unroll
                for (int j = 0; j < 8; j++) {
                    unsigned e = encf(v[j]);
                    if (e > tm[j]) tm[j] = e;
                }
            }
        }
    }
    if (COLMAX) {
        __shared__ unsigned smax[128];
        for (int t = tid; t < 128; t += 256) smax[t] = 0u;
        __syncthreads();
#pragma unroll
        for (int j = 0; j < 8; j++) atomicMax(&smax[tc * 8 + j], tm[j]);
        __syncthreads();
        for (int t = tid; t < 128; t += 256)
            if (smax[t]) atomicMax(&cm[t], smax[t]);
    }
}

// ---------------- iter-1 edge pass: scatter-max messages into cf1 ----------------
// msg[e] = leaky(P1[from] + P2[to] + ef[e]@We.T + b); cf1[from] = max(cf1[from], msg, 0)
__global__ void edge_scatter(const float* __restrict__ P1, const float* __restrict__ P2,
                             const int* __restrict__ eidx, const float* __restrict__ ef,
                             const float* __restrict__ Wit,  // edge_w[0] base, ld=260
                             const float* __restrict__ bit,  // edge_b[0]
                             float* __restrict__ cf1, int nE)
{
    __shared__ float wesT[4][128];
    __shared__ float bsh[128];
    const int tid = threadIdx.x;
    if (tid < 128) {
#pragma unroll
        for (int k = 0; k < 4; k++) wesT[k][tid] = Wit[tid * LDE + 256 + k];
        bsh[tid] = bit[tid];
    }
    __syncthreads();
    const int warp = tid >> 5, lane = tid & 31;
    const int h0 = lane * 4;
    float wk[4][4], bb[4];
#pragma unroll
    for (int j = 0; j < 4; j++) {
        bb[j] = bsh[h0 + j];
#pragma unroll
        for (int k = 0; k < 4; k++) wk[k][j] = wesT[k][h0 + j];
    }

    for (int e = blockIdx.x * 8 + warp; e < nE; e += gridDim.x * 8) {
        int from = eidx[2 * e];
        int to = eidx[2 * e + 1];
        float4 e4 = *reinterpret_cast<const float4*>(ef + 4 * e);
        float4 p1 = *reinterpret_cast<const float4*>(P1 + from * H_DIM + h0);
        float4 p2 = *reinterpret_cast<const float4*>(P2 + to * H_DIM + h0);
        float pa[4] = {p1.x + p2.x, p1.y + p2.y, p1.z + p2.z, p1.w + p2.w};
        int* dst = reinterpret_cast<int*>(cf1 + from * H_DIM + h0);
#pragma unroll
        for (int j = 0; j < 4; j++) {
            float m = pa[j] + e4.x * wk[0][j] + e4.y * wk[1][j] +
                      e4.z * wk[2][j] + e4.w * wk[3][j] + bb[j];
            // leaky(m) <= 0 never beats the 0-initialized target, so only
            // positive m (where leaky is identity) can update.
            if (m > 0.f) atomicMax(dst + j, __float_as_int(m));
        }
    }
}

// ---------------- iter-2 edge pass: column-max of messages only ----------------
__global__ void edge_colmax(const float* __restrict__ P1, const float* __restrict__ P2,
                            const int* __restrict__ eidx, const float* __restrict__ ef,
                            const float* __restrict__ Wit,  // edge_w[1] base
                            const float* __restrict__ bit,  // edge_b[1]
                            unsigned* __restrict__ cm, int nE)
{
    __shared__ float wesT[4][128];
    __shared__ float bsh[128];
    __shared__ unsigned smax[128];
    const int tid = threadIdx.x;
    if (tid < 128) {
#pragma unroll
        for (int k = 0; k < 4; k++) wesT[k][tid] = Wit[tid * LDE + 256 + k];
        bsh[tid] = bit[tid];
    }
    for (int t = tid; t < 128; t += 256) smax[t] = 0u;
    __syncthreads();
    const int warp = tid >> 5, lane = tid & 31;
    const int h0 = lane * 4;
    float wk[4][4], bb[4];
#pragma unroll
    for (int j = 0; j < 4; j++) {
        bb[j] = bsh[h0 + j];
#pragma unroll
        for (int k = 0; k < 4; k++) wk[k][j] = wesT[k][h0 + j];
    }
    float rm[4] = {NEG_INF, NEG_INF, NEG_INF, NEG_INF};

    for (int e = blockIdx.x * 8 + warp; e < nE; e += gridDim.x * 8) {
        int from = eidx[2 * e];
        int to = eidx[2 * e + 1];
        float4 e4 = *reinterpret_cast<const float4*>(ef + 4 * e);
        float4 p1 = *reinterpret_cast<const float4*>(P1 + from * H_DIM + h0);
        float4 p2 = *reinterpret_cast<const float4*>(P2 + to * H_DIM + h0);
        float pa[4] = {p1.x + p2.x, p1.y + p2.y, p1.z + p2.z, p1.w + p2.w};
#pragma unroll
        for (int j = 0; j < 4; j++) {
            float m = pa[j] + e4.x * wk[0][j] + e4.y * wk[1][j] +
                      e4.z * wk[2][j] + e4.w * wk[3][j] + bb[j];
            float lm = leaky(m);
            rm[j] = fmaxf(rm[j], lm);
        }
    }
#pragma unroll
    for (int j = 0; j < 4; j++)
        if (rm[j] > NEG_INF) atomicMax(&smax[h0 + j], encf(rm[j]));
    __syncthreads();
    if (tid < 128 && smax[tid]) atomicMax(&cm[tid], smax[tid]);
}

// ---------------- column max of cf1 (values >= 0) ----------------
__global__ void colmax128(const float* __restrict__ x, int N, unsigned* __restrict__ cm)
{
    int h = threadIdx.x;  // 128 threads
    float m = NEG_INF;
    for (int row = blockIdx.x; row < N; row += gridDim.x)
        m = fmaxf(m, x[row * H_DIM + h]);
    if (m > NEG_INF) atomicMax(&cm[h], encf(m));
}

// ---------------- parent_feat ----------------
__global__ void final_feat(const unsigned* __restrict__ cm,
                           const float* __restrict__ sec_w,
                           const float* __restrict__ sec_b,
                           float* __restrict__ out)
{
    __shared__ float ipf[384];
    int h = threadIdx.x;  // 128
    ipf[h]       = decf(cm[h]);                    // ipf0 (stage A colmax)
    ipf[128 + h] = decf(cm[128 + h]);              // ipf1 (cf1 colmax, >=0)
    ipf[256 + h] = fmaxf(0.f, decf(cm[256 + h]));  // ipf2 = max(0, msg colmax)
    __syncthreads();
    float s = sec_b[h];
    const float* wr = sec_w + h * 384;
#pragma unroll 8
    for (int j = 0; j < 384; j++) s = fmaf(ipf[j], wr[j], s);
    out[h] = leaky(s);
}

// ---------------- parent_geo_feat ----------------
__global__ void final_geo(const unsigned* __restrict__ cm,  // +384: geo, +512: skip
                          const float* __restrict__ sgw, const float* __restrict__ sgb,
                          const float* __restrict__ gnw, const float* __restrict__ gnb,
                          float* __restrict__ out)
{
    __shared__ float pg[128];
    __shared__ float tbuf[128];
    int h = threadIdx.x;  // 128
    pg[h] = leaky(decf(cm[384 + h]));
    float sg = leaky(decf(cm[512 + h]));
    __syncthreads();
    float t = sgb[h];
    const float* wr = sgw + h * 128;
#pragma unroll 8
    for (int j = 0; j < 128; j++) t = fmaf(pg[j], wr[j], t);
    tbuf[h] = t;
    __syncthreads();
    int g0 = (h >> 3) << 3;  // group of 8 channels
    float mu = 0.f;
#pragma unroll
    for (int j = 0; j < 8; j++) mu += tbuf[g0 + j];
    mu *= 0.125f;
    float var = 0.f;
#pragma unroll
    for (int j = 0; j < 8; j++) {
        float d = tbuf[g0 + j] - mu;
        var = fmaf(d, d, var);
    }
    var *= 0.125f;
    float xn = (t - mu) * rsqrtf(var + 1e-5f);
    float y = xn * gnw[h] + gnb[h];
    out[128 + h] = leaky(sg + y);
}

// ---------------- launch ----------------
extern "C" void kernel_launch(void* const* d_in, const int* in_sizes, int n_in,
                              void* d_out, int out_size)
{
    const float* child_feats = (const float*)d_in[0];   // (1,N,162)
    const float* child_geo   = (const float*)d_in[1];   // (1,N,128)
    const float* exists      = (const float*)d_in[2];   // (1,N,1)
    const float* ef          = (const float*)d_in[3];   // (1,E,4)
    const int*   eidx        = (const int*)d_in[4];     // (1,E,2)
    const float* op_w  = (const float*)d_in[5];         // (128,162)
    const float* op_b  = (const float*)d_in[6];
    const float* sec_w = (const float*)d_in[7];         // (128,384)
    const float* sec_b = (const float*)d_in[8];
    const float* ew    = (const float*)d_in[9];         // (2,128,260)
    const float* eb    = (const float*)d_in[10];        // (2,128)
    const float* gw    = (const float*)d_in[11];        // (128,128)
    const float* gb    = (const float*)d_in[12];
    const float* sgw   = (const float*)d_in[13];        // (128,128)
    const float* sgb   = (const float*)d_in[14];
    const float* gnw   = (const float*)d_in[15];
    const float* gnb   = (const float*)d_in[16];
    const float* skw   = (const float*)d_in[17];        // (128,128)
    const float* skb   = (const float*)d_in[18];
    float* out = (float*)d_out;

    const int N  = in_sizes[2];       // 20000
    const int nE = in_sizes[4] / 2;   // 320000

    float *cf0, *P1, *P2, *cf1;
    unsigned* cm;
    cudaGetSymbolAddress((void**)&cf0, g_cf0);
    cudaGetSymbolAddress((void**)&P1, g_P1);
    cudaGetSymbolAddress((void**)&P2, g_P2);
    cudaGetSymbolAddress((void**)&cf1, g_cf1);
    cudaGetSymbolAddress((void**)&cm, g_cm);

    const int gemmBlocks = (N + 127) / 128;

    // 0) zero cf1 + colmax slots
    init_zero<<<1280, 256>>>(cf1, cm);

    // 1) stage A: cf0 = (child_feats @ op_w.T + op_b) * exists ; colmax -> cm[0:128)
    node_gemm2<true, true, true, true, false><<<gemmBlocks, 256>>>(
        child_feats, N, KIN, KIN, op_w, KIN, op_b, exists, cf0, cm);

    // 2) P1 = cf0 @ edge_w[0][:,0:128].T ; P2 = cf0 @ edge_w[0][:,128:256].T
    node_gemm2<true, false, false, false, true><<<gemmBlocks, 256>>>(
        cf0, N, H_DIM, H_DIM, ew, LDE, nullptr, nullptr, P1, nullptr);
    node_gemm2<true, false, false, false, true><<<gemmBlocks, 256>>>(
        cf0, N, H_DIM, H_DIM, ew + 128, LDE, nullptr, nullptr, P2, nullptr);

    // 3) iter-1 edge pass: scatter-max into cf1
    edge_scatter<<<3040, 256>>>(P1, P2, eidx, ef, ew, eb, cf1, nE);

    // 4) ipf1 = colmax(cf1) -> cm[128:256)
    colmax128<<<512, 128>>>(cf1, N, cm + 128);

    // 5) Q1/Q2 from cf1 with edge_w[1] (reuse P buffers)
    node_gemm2<true, false, false, false, true><<<gemmBlocks, 256>>>(
        cf1, N, H_DIM, H_DIM, ew + LDE * 128, LDE, nullptr, nullptr, P1, nullptr);
    node_gemm2<true, false, false, false, true><<<gemmBlocks, 256>>>(
        cf1, N, H_DIM, H_DIM, ew + LDE * 128 + 128, LDE, nullptr, nullptr, P2, nullptr);

    // 6) iter-2 edge pass: msg colmax only -> cm[256:384)
    edge_colmax<<<1184, 256>>>(P1, P2, eidx, ef, ew + LDE * 128, eb + 128, cm + 256, nE);

    // 7) geo + skip column maxes (no store) -> cm[384:512), cm[512:640)
    node_gemm2<false, true, true, true, true><<<gemmBlocks, 256>>>(
        child_geo, N, H_DIM, H_DIM, gw, H_DIM, gb, exists, nullptr, cm + 384);
    node_gemm2<false, true, true, true, true><<<gemmBlocks, 256>>>(
        child_geo, N, H_DIM, H_DIM, skw, H_DIM, skb, exists, nullptr, cm + 512);

    // 8) heads
    final_feat<<<1, 128>>>(cm, sec_w, sec_b, out);
    final_geo<<<1, 128>>>(cm, sgw, sgb, gnw, gnb, out);
}